// round 9
// baseline (speedup 1.0000x reference)
#include <cuda_runtime.h>
#include <cuda_fp16.h>

#define NN 100000
#define EE 1600000
#define HH 64

// Scratch (device globals; no allocation allowed)
__device__ float g_h[NN * HH];
__device__ float g_agg[NN * HH];
__device__ unsigned long long g_eah[(size_t)EE * 16];  // fp16 copy of edge_attr: 16 ull = 64 halves per edge

__device__ __forceinline__ float frelu(float x) { return x > 0.f ? x : 0.f; }

typedef unsigned long long ull;

// ---- packed f32x2 helpers (FFMA2 — only reachable via PTX) -----------------
__device__ __forceinline__ ull pk2(float lo, float hi) {
    ull r;
    asm("mov.b64 %0, {%1,%2};" : "=l"(r) : "f"(lo), "f"(hi));
    return r;
}
__device__ __forceinline__ void upk2(ull v, float& lo, float& hi) {
    asm("mov.b64 {%0,%1}, %2;" : "=f"(lo), "=f"(hi) : "l"(v));
}
__device__ __forceinline__ ull ffma2(ull a, ull b, ull c) {
    ull d;
    asm("fma.rn.f32x2 %0, %1, %2, %3;" : "=l"(d) : "l"(a), "l"(b), "l"(c));
    return d;
}

__device__ __forceinline__ unsigned h2_bits(float a, float b) {
    __half2 h = __floats2half2_rn(a, b);
    return *reinterpret_cast<unsigned*>(&h);
}
__device__ __forceinline__ float2 bits_h2f(unsigned u) {
    __half2 h = *reinterpret_cast<__half2*>(&u);
    return __half22float2(h);
}

// ---------------------------------------------------------------------------
// Edge pass 1: fp32 ea read (exact math) + fused fp16 down-convert of ea for
// passes 2-3. R3/R8 shape: 8 threads/edge, 2 float4 chunks each.
// ---------------------------------------------------------------------------
__global__ void __launch_bounds__(256) edge_kernel_first(
    const float4* __restrict__ h,
    const float4* __restrict__ ea,
    const int* __restrict__ src,
    const int* __restrict__ dst,
    float4* __restrict__ agg,
    ull* __restrict__ eah)
{
    int t = blockIdx.x * 256 + threadIdx.x;
    int e = t >> 3;
    if (e >= EE) return;
    int c = t & 7;

    int s = __ldg(&src[e]);
    int d = __ldg(&dst[e]);

    float4 a0 = __ldcs(&ea[(size_t)e * 16 + c]);
    float4 a1 = __ldcs(&ea[(size_t)e * 16 + c + 8]);
    float4 h0 = __ldcg(&h[(size_t)s * 16 + c]);
    float4 h1 = __ldcg(&h[(size_t)s * 16 + c + 8]);

    // fused fp16 conversion (streaming store; 1 ull = 4 halves per chunk)
    ull p0 = ((ull)h2_bits(a0.z, a0.w) << 32) | h2_bits(a0.x, a0.y);
    ull p1 = ((ull)h2_bits(a1.z, a1.w) << 32) | h2_bits(a1.x, a1.y);
    __stcs(&eah[(size_t)e * 16 + c], p0);
    __stcs(&eah[(size_t)e * 16 + c + 8], p1);

    float4 m0, m1;
    m0.x = frelu(a0.x + h0.x); m0.y = frelu(a0.y + h0.y);
    m0.z = frelu(a0.z + h0.z); m0.w = frelu(a0.w + h0.w);
    m1.x = frelu(a1.x + h1.x); m1.y = frelu(a1.y + h1.y);
    m1.z = frelu(a1.z + h1.z); m1.w = frelu(a1.w + h1.w);

    atomicAdd(&agg[(size_t)d * 16 + c], m0);
    atomicAdd(&agg[(size_t)d * 16 + c + 8], m1);
}

// ---------------------------------------------------------------------------
// Edge passes 2-3: fp16 ea read (half the DRAM stream). Same mapping.
// ---------------------------------------------------------------------------
__global__ void __launch_bounds__(256) edge_kernel_half(
    const float4* __restrict__ h,
    const ull* __restrict__ eah,
    const int* __restrict__ src,
    const int* __restrict__ dst,
    float4* __restrict__ agg)
{
    int t = blockIdx.x * 256 + threadIdx.x;
    int e = t >> 3;
    if (e >= EE) return;
    int c = t & 7;

    int s = __ldg(&src[e]);
    int d = __ldg(&dst[e]);

    ull p0 = __ldcs(&eah[(size_t)e * 16 + c]);
    ull p1 = __ldcs(&eah[(size_t)e * 16 + c + 8]);
    float4 h0 = __ldcg(&h[(size_t)s * 16 + c]);
    float4 h1 = __ldcg(&h[(size_t)s * 16 + c + 8]);

    float2 a00 = bits_h2f((unsigned)p0);
    float2 a01 = bits_h2f((unsigned)(p0 >> 32));
    float2 a10 = bits_h2f((unsigned)p1);
    float2 a11 = bits_h2f((unsigned)(p1 >> 32));

    float4 m0, m1;
    m0.x = frelu(a00.x + h0.x); m0.y = frelu(a00.y + h0.y);
    m0.z = frelu(a01.x + h0.z); m0.w = frelu(a01.y + h0.w);
    m1.x = frelu(a10.x + h1.x); m1.y = frelu(a10.y + h1.y);
    m1.z = frelu(a11.x + h1.z); m1.w = frelu(a11.y + h1.w);

    atomicAdd(&agg[(size_t)d * 16 + c], m0);
    atomicAdd(&agg[(size_t)d * 16 + c + 8], m1);
}

// ---------------------------------------------------------------------------
// Conv MLP kernel (R8, measured best): FFMA2, k-packed, no transpose.
// out = relu_opt(relu(in@W1+b1)@W2+b2) + resid
// ---------------------------------------------------------------------------
#define MLP_SMEM_FLOATS (4096 + 4096 + 64 + 64 + 64 * 64)
__global__ void __launch_bounds__(256) mlp_kernel(
    const float* __restrict__ in,
    const float* __restrict__ resid,
    const float* __restrict__ W1, const float* __restrict__ b1,
    const float* __restrict__ W2, const float* __restrict__ b2,
    float* __restrict__ out1, float* __restrict__ out2,
    int relu_out)
{
    extern __shared__ float sm[];
    float* sW1 = sm;              // 64*64
    float* sW2 = sm + 4096;       // 64*64
    float* sb1 = sm + 8192;       // 64
    float* sb2 = sm + 8256;       // 64
    float* sIn = sm + 8320;       // [node][64], natural layout

    const int tid = threadIdx.x;
    const int base = blockIdx.x * 64;

    for (int i = tid; i < 4096; i += 256) { sW1[i] = W1[i]; sW2[i] = W2[i]; }
    if (tid < 64) { sb1[tid] = b1[tid]; sb2[tid] = b2[tid]; }
    for (int i = tid; i < 64 * 16; i += 256) {
        int nd = i >> 4, c = i & 15;
        float4 v = make_float4(0.f, 0.f, 0.f, 0.f);
        if (base + nd < NN) v = ((const float4*)in)[(size_t)(base + nd) * 16 + c];
        ((float4*)(sIn + nd * 64))[c] = v;
    }
    __syncthreads();

    const int w = tid >> 5, l = tid & 31;
    const int ln0 = w * 8;

    ull acc0[8], acc1[8];
    {
        ull bb0 = pk2(sb1[l], 0.f);
        ull bb1 = pk2(sb1[l + 32], 0.f);
#pragma unroll
        for (int j = 0; j < 8; j++) { acc0[j] = bb0; acc1[j] = bb1; }
    }

#pragma unroll 8
    for (int k = 0; k < 64; k += 2) {
        ull w0p = pk2(sW1[k * 64 + l],      sW1[(k + 1) * 64 + l]);
        ull w1p = pk2(sW1[k * 64 + l + 32], sW1[(k + 1) * 64 + l + 32]);
#pragma unroll
        for (int j = 0; j < 8; j++) {
            ull vp = *(const ull*)&sIn[(ln0 + j) * 64 + k];
            acc0[j] = ffma2(vp, w0p, acc0[j]);
            acc1[j] = ffma2(vp, w1p, acc1[j]);
        }
    }

    __syncwarp();
#pragma unroll
    for (int j = 0; j < 8; j++) {
        float x0, x1, y0, y1;
        upk2(acc0[j], x0, x1);
        upk2(acc1[j], y0, y1);
        sIn[(ln0 + j) * 64 + l]      = frelu(x0 + x1);
        sIn[(ln0 + j) * 64 + l + 32] = frelu(y0 + y1);
    }
    __syncwarp();

    {
        ull bb0 = pk2(sb2[l], 0.f);
        ull bb1 = pk2(sb2[l + 32], 0.f);
#pragma unroll
        for (int j = 0; j < 8; j++) { acc0[j] = bb0; acc1[j] = bb1; }
    }

#pragma unroll 8
    for (int k = 0; k < 64; k += 2) {
        ull w0p = pk2(sW2[k * 64 + l],      sW2[(k + 1) * 64 + l]);
        ull w1p = pk2(sW2[k * 64 + l + 32], sW2[(k + 1) * 64 + l + 32]);
#pragma unroll
        for (int j = 0; j < 8; j++) {
            ull vp = *(const ull*)&sIn[(ln0 + j) * 64 + k];
            acc0[j] = ffma2(vp, w0p, acc0[j]);
            acc1[j] = ffma2(vp, w1p, acc1[j]);
        }
    }

#pragma unroll
    for (int j = 0; j < 8; j++) {
        int nd = base + ln0 + j;
        if (nd < NN) {
            float x0, x1, y0, y1;
            upk2(acc0[j], x0, x1);
            upk2(acc1[j], y0, y1);
            float v0 = x0 + x1, v1 = y0 + y1;
            if (relu_out) { v0 = frelu(v0); v1 = frelu(v1); }
            v0 += resid[(size_t)nd * 64 + l];
            v1 += resid[(size_t)nd * 64 + l + 32];
            out1[(size_t)nd * 64 + l] = v0;
            out1[(size_t)nd * 64 + l + 32] = v1;
            if (out2) { out2[(size_t)nd * 64 + l] = v0; out2[(size_t)nd * 64 + l + 32] = v1; }
        }
    }
}

// ---------------------------------------------------------------------------
// Init kernel (R8): h0 = relu(concat(emb[z],t)@rw1+rb1)@rw2+rb2
// ---------------------------------------------------------------------------
#define INIT_SMEM_FLOATS (65 * 64 + 4096 + 64 + 64 + 64 * 68)
__global__ void __launch_bounds__(256) init_kernel(
    const int* __restrict__ z,
    const float* __restrict__ t,
    const float* __restrict__ emb,
    const float* __restrict__ W1, const float* __restrict__ b1,
    const float* __restrict__ W2, const float* __restrict__ b2,
    float* __restrict__ out1, float* __restrict__ out2)
{
    extern __shared__ float sm[];
    float* sW1 = sm;                    // 65*64 = 4160
    float* sW2 = sm + 4160;             // 64*64
    float* sb1 = sm + 8256;             // 64
    float* sb2 = sm + 8320;             // 64
    float* sIn = sm + 8384;             // [node][68] (65 used)
    __shared__ int sZ[64];

    const int tid = threadIdx.x;
    const int base = blockIdx.x * 64;

    for (int i = tid; i < 4160; i += 256) sW1[i] = W1[i];
    for (int i = tid; i < 4096; i += 256) sW2[i] = W2[i];
    if (tid < 64) {
        sb1[tid] = b1[tid]; sb2[tid] = b2[tid];
        int nd = base + tid;
        sZ[tid] = (nd < NN) ? z[nd] : 0;
        sIn[tid * 68 + 64] = (nd < NN) ? t[nd] : 0.f;
    }
    __syncthreads();

    for (int i = tid; i < 64 * 16; i += 256) {
        int nd = i >> 4, c = i & 15;
        float4 v = ((const float4*)emb)[(size_t)sZ[nd] * 16 + c];
        ((float4*)(sIn + nd * 68))[c] = v;
    }
    __syncthreads();

    const int w = tid >> 5, l = tid & 31;
    const int ln0 = w * 8;

    ull acc0[8], acc1[8];
    {
        ull bb0 = pk2(sb1[l], 0.f);
        ull bb1 = pk2(sb1[l + 32], 0.f);
#pragma unroll
        for (int j = 0; j < 8; j++) { acc0[j] = bb0; acc1[j] = bb1; }
    }

#pragma unroll 8
    for (int k = 0; k < 64; k += 2) {
        ull w0p = pk2(sW1[k * 64 + l],      sW1[(k + 1) * 64 + l]);
        ull w1p = pk2(sW1[k * 64 + l + 32], sW1[(k + 1) * 64 + l + 32]);
#pragma unroll
        for (int j = 0; j < 8; j++) {
            ull vp = *(const ull*)&sIn[(ln0 + j) * 68 + k];
            acc0[j] = ffma2(vp, w0p, acc0[j]);
            acc1[j] = ffma2(vp, w1p, acc1[j]);
        }
    }
    {   // k = 64 tail (the t column): packed (v,0)*(w,w) adds to lo only
        ull w0p = pk2(sW1[64 * 64 + l],      sW1[64 * 64 + l]);
        ull w1p = pk2(sW1[64 * 64 + l + 32], sW1[64 * 64 + l + 32]);
#pragma unroll
        for (int j = 0; j < 8; j++) {
            ull vp = pk2(sIn[(ln0 + j) * 68 + 64], 0.f);
            acc0[j] = ffma2(vp, w0p, acc0[j]);
            acc1[j] = ffma2(vp, w1p, acc1[j]);
        }
    }

    __syncwarp();
#pragma unroll
    for (int j = 0; j < 8; j++) {
        float x0, x1, y0, y1;
        upk2(acc0[j], x0, x1);
        upk2(acc1[j], y0, y1);
        sIn[(ln0 + j) * 68 + l]      = frelu(x0 + x1);
        sIn[(ln0 + j) * 68 + l + 32] = frelu(y0 + y1);
    }
    __syncwarp();

    {
        ull bb0 = pk2(sb2[l], 0.f);
        ull bb1 = pk2(sb2[l + 32], 0.f);
#pragma unroll
        for (int j = 0; j < 8; j++) { acc0[j] = bb0; acc1[j] = bb1; }
    }

#pragma unroll 8
    for (int k = 0; k < 64; k += 2) {
        ull w0p = pk2(sW2[k * 64 + l],      sW2[(k + 1) * 64 + l]);
        ull w1p = pk2(sW2[k * 64 + l + 32], sW2[(k + 1) * 64 + l + 32]);
#pragma unroll
        for (int j = 0; j < 8; j++) {
            ull vp = *(const ull*)&sIn[(ln0 + j) * 68 + k];
            acc0[j] = ffma2(vp, w0p, acc0[j]);
            acc1[j] = ffma2(vp, w1p, acc1[j]);
        }
    }

#pragma unroll
    for (int j = 0; j < 8; j++) {
        int nd = base + ln0 + j;
        if (nd < NN) {
            float x0, x1, y0, y1;
            upk2(acc0[j], x0, x1);
            upk2(acc1[j], y0, y1);
            float v0 = x0 + x1, v1 = y0 + y1;
            out1[(size_t)nd * 64 + l] = v0;
            out1[(size_t)nd * 64 + l + 32] = v1;
            out2[(size_t)nd * 64 + l] = v0;
            out2[(size_t)nd * 64 + l + 32] = v1;
        }
    }
}

// ---------------------------------------------------------------------------
// Launch
// ---------------------------------------------------------------------------
extern "C" void kernel_launch(void* const* d_in, const int* in_sizes, int n_in,
                              void* d_out, int out_size)
{
    const int*   z    = (const int*)  d_in[0];
    const int*   ei   = (const int*)  d_in[1];   // [2, E]: src = ei, dst = ei + EE
    const float* ea   = (const float*)d_in[2];
    const float* t    = (const float*)d_in[3];
    const float* emb  = (const float*)d_in[4];
    const float* rw1  = (const float*)d_in[5];
    const float* rb1  = (const float*)d_in[6];
    const float* rw2  = (const float*)d_in[7];
    const float* rb2  = (const float*)d_in[8];
    const float* cw1  = (const float*)d_in[9];
    const float* cb1  = (const float*)d_in[10];
    const float* cw2  = (const float*)d_in[11];
    const float* cb2  = (const float*)d_in[12];
    float* out = (float*)d_out;

    float* hp = nullptr;
    float* ap = nullptr;
    ull*   ehp = nullptr;
    cudaGetSymbolAddress((void**)&hp, g_h);
    cudaGetSymbolAddress((void**)&ap, g_agg);
    cudaGetSymbolAddress((void**)&ehp, g_eah);

    const int init_smem = INIT_SMEM_FLOATS * sizeof(float);
    const int mlp_smem  = MLP_SMEM_FLOATS * sizeof(float);
    cudaFuncSetAttribute(init_kernel, cudaFuncAttributeMaxDynamicSharedMemorySize, init_smem);
    cudaFuncSetAttribute(mlp_kernel,  cudaFuncAttributeMaxDynamicSharedMemorySize, mlp_smem);

    const int nblk_node = (NN + 63) / 64;
    const int nblk_edge = (EE * 8 + 255) / 256;

    init_kernel<<<nblk_node, 256, init_smem>>>(z, t, emb, rw1, rb1, rw2, rb2, hp, ap);

    for (int li = 0; li < 3; li++) {
        if (li == 0) {
            edge_kernel_first<<<nblk_edge, 256>>>((const float4*)hp, (const float4*)ea,
                                                  ei, ei + EE, (float4*)ap, ehp);
        } else {
            edge_kernel_half<<<nblk_edge, 256>>>((const float4*)hp, ehp,
                                                 ei, ei + EE, (float4*)ap);
        }
        const float* W1 = cw1 + li * 4096;
        const float* b1 = cb1 + li * 64;
        const float* W2 = cw2 + li * 4096;
        const float* b2 = cb2 + li * 64;
        if (li < 2) {
            mlp_kernel<<<nblk_node, 256, mlp_smem>>>(ap, hp, W1, b1, W2, b2, hp, ap, 1);
        } else {
            mlp_kernel<<<nblk_node, 256, mlp_smem>>>(ap, hp, W1, b1, W2, b2, out, nullptr, 0);
        }
    }
}